// round 7
// baseline (speedup 1.0000x reference)
#include <cuda_runtime.h>

#define B 8
#define M 8192
#define N 8192
#define SPLITS 64
#define ROWS (M / SPLITS)            // 128 rows per split
#define TPB 128
#define COLS_PER_BLOCK (TPB * 4)     // 512 columns per block (4 floats per thread)
#define NBLK (N / COLS_PER_BLOCK)    // 16 -> grid 16x64 = 1024 blocks

// L2-resident accumulator: [B][N] floats = 256 KB device scratch.
__device__ float g_accum[(size_t)B * N];

// Packed fp32x2 FMA: d = a*b + d  (sm_103a FFMA2, only reachable via PTX)
#define FMA2(d, a, b) \
    asm("fma.rn.f32x2 %0, %1, %2, %0;" : "+l"(d) : "l"(a), "l"(b))

__global__ void __launch_bounds__(256)
snn_zero()
{
    const int idx = blockIdx.x * 256 + threadIdx.x;   // over B*N
    g_accum[idx] = 0.f;
}

__global__ void __launch_bounds__(TPB, 7)
snn_gemv_split(const float* __restrict__ pre,   // [B][M]
               const float* __restrict__ W)     // [M][N] row-major
{
    // Pre-spikes pre-duplicated: pre_s2[r][b] = {p, p} (64-bit), so packed
    // multipliers come straight from LDS.128. 128*8*8 = 8 KB smem.
    __shared__ unsigned long long pre_s2[ROWS][B];

    const int nb  = blockIdx.x;
    const int s   = blockIdx.y;
    const int tid = threadIdx.x;
    const int m0  = s * ROWS;

    // tid == row (ROWS == TPB == 128)
    #pragma unroll
    for (int b = 0; b < B; b++) {
        float p = pre[b * M + m0 + tid];
        float2 pp = make_float2(p, p);
        pre_s2[tid][b] = *reinterpret_cast<unsigned long long*>(&pp);
    }
    __syncthreads();

    const int n0 = nb * COLS_PER_BLOCK + tid * 4;
    const ulonglong2* Wp =
        reinterpret_cast<const ulonglong2*>(W + (size_t)m0 * N + n0);
    const size_t S16 = N / 4;        // row stride in 16-byte (ulonglong2) units

    // acc[b][0] = packed cols {0,1}, acc[b][1] = packed cols {2,3}
    unsigned long long acc[B][2];
    #pragma unroll
    for (int b = 0; b < B; b++) { acc[b][0] = 0ull; acc[b][1] = 0ull; }

    // One row of packed-FMA work; W is an ulonglong2 (4 cols as 2 packed pairs)
    #define DO_ROW(WV, MI) do {                                              \
        const ulonglong2* ps =                                               \
            reinterpret_cast<const ulonglong2*>(&pre_s2[(MI)][0]);           \
        ulonglong2 pa = ps[0];  /* batches 0,1 */                            \
        ulonglong2 pb = ps[1];  /* batches 2,3 */                            \
        ulonglong2 pc = ps[2];  /* batches 4,5 */                            \
        ulonglong2 pd = ps[3];  /* batches 6,7 */                            \
        FMA2(acc[0][0], (WV).x, pa.x); FMA2(acc[0][1], (WV).y, pa.x);        \
        FMA2(acc[1][0], (WV).x, pa.y); FMA2(acc[1][1], (WV).y, pa.y);        \
        FMA2(acc[2][0], (WV).x, pb.x); FMA2(acc[2][1], (WV).y, pb.x);        \
        FMA2(acc[3][0], (WV).x, pb.y); FMA2(acc[3][1], (WV).y, pb.y);        \
        FMA2(acc[4][0], (WV).x, pc.x); FMA2(acc[4][1], (WV).y, pc.x);        \
        FMA2(acc[5][0], (WV).x, pc.y); FMA2(acc[5][1], (WV).y, pc.y);        \
        FMA2(acc[6][0], (WV).x, pd.x); FMA2(acc[6][1], (WV).y, pd.x);        \
        FMA2(acc[7][0], (WV).x, pd.y); FMA2(acc[7][1], (WV).y, pd.y);        \
    } while (0)

    // Explicit 4-deep load batching: 4 independent LDG.128s issued in program
    // order before any FMA consumes them -> MLP >= 4 per warp.
    #pragma unroll 1
    for (int m = 0; m < ROWS; m += 4) {
        ulonglong2 w0 = Wp[(size_t)(m + 0) * S16];
        ulonglong2 w1 = Wp[(size_t)(m + 1) * S16];
        ulonglong2 w2 = Wp[(size_t)(m + 2) * S16];
        ulonglong2 w3 = Wp[(size_t)(m + 3) * S16];
        DO_ROW(w0, m + 0);
        DO_ROW(w1, m + 1);
        DO_ROW(w2, m + 2);
        DO_ROW(w3, m + 3);
    }
    #undef DO_ROW

    // Epilogue: accumulate into the 256 KB L2-resident buffer via REDG
    // (atomicAdd with unused return -> RED.ADD, no read round-trip).
    #pragma unroll
    for (int b = 0; b < B; b++) {
        float2 lo = *reinterpret_cast<float2*>(&acc[b][0]);
        float2 hi = *reinterpret_cast<float2*>(&acc[b][1]);
        float* dst = &g_accum[(size_t)b * N + n0];
        atomicAdd(dst + 0, lo.x);
        atomicAdd(dst + 1, lo.y);
        atomicAdd(dst + 2, hi.x);
        atomicAdd(dst + 3, hi.y);
    }
}

__global__ void __launch_bounds__(256)
snn_finalize(const float* __restrict__ thr,     // [B][N]
             const float* __restrict__ cst,     // [B][N]
             float* __restrict__ out)           // [B][N]
{
    const int idx = blockIdx.x * 256 + threadIdx.x;   // over B*N (65536)
    float o = g_accum[idx] + cst[idx] - thr[idx];
    out[idx] = fminf(fmaxf(o, 0.f), 0.9f);
}

extern "C" void kernel_launch(void* const* d_in, const int* in_sizes, int n_in,
                              void* d_out, int out_size)
{
    const float* pre = (const float*)d_in[0];   // pre_spikes [8,1,8192]
    const float* W   = (const float*)d_in[1];   // W [8192,8192]
    const float* thr = (const float*)d_in[2];   // thr [8,1,8192]
    const float* cst = (const float*)d_in[3];   // const_inp [8,1,8192]
    float* out = (float*)d_out;                 // [8,1,8192]

    snn_zero<<<(B * N) / 256, 256>>>();

    dim3 grid(NBLK, SPLITS);                    // 16 x 64 = 1024 blocks
    snn_gemv_split<<<grid, TPB>>>(pre, W);

    snn_finalize<<<(B * N) / 256, 256>>>(thr, cst, out);
}

// round 8
// speedup vs baseline: 1.0948x; 1.0948x over previous
#include <cuda_runtime.h>

#define B 8
#define M 8192
#define N 8192
#define SPLITS 64
#define ROWS (M / SPLITS)            // 128 rows per split
#define TPB 128
#define COLS_PER_BLOCK (TPB * 4)     // 512 columns per block (4 floats per thread)
#define NBLK (N / COLS_PER_BLOCK)    // 16 -> grid 16x64 = 1024 blocks

// Split-K partial sums: [SPLITS][B][N] floats = 16 MB device scratch.
__device__ float g_part[(size_t)SPLITS * B * N];

// Packed fp32x2 FMA: d = a*b + d  (sm_103a FFMA2, only reachable via PTX)
#define FMA2(d, a, b) \
    asm("fma.rn.f32x2 %0, %1, %2, %0;" : "+l"(d) : "l"(a), "l"(b))

__global__ void __launch_bounds__(TPB, 7)
snn_gemv_split(const float* __restrict__ pre,   // [B][M]
               const float* __restrict__ W)     // [M][N] row-major
{
    // Pre-spikes pre-duplicated: pre_s2[r][b] = {p, p} (64-bit), so packed
    // multipliers come straight from LDS.128. 128*8*8 = 8 KB smem.
    __shared__ unsigned long long pre_s2[ROWS][B];

    const int nb  = blockIdx.x;
    const int s   = blockIdx.y;
    const int tid = threadIdx.x;
    const int m0  = s * ROWS;

    // tid == row (ROWS == TPB == 128)
    #pragma unroll
    for (int b = 0; b < B; b++) {
        float p = pre[b * M + m0 + tid];
        float2 pp = make_float2(p, p);
        pre_s2[tid][b] = *reinterpret_cast<unsigned long long*>(&pp);
    }
    __syncthreads();

    const int n0 = nb * COLS_PER_BLOCK + tid * 4;
    const ulonglong2* Wp =
        reinterpret_cast<const ulonglong2*>(W + (size_t)m0 * N + n0);
    const size_t S16 = N / 4;        // row stride in 16-byte (ulonglong2) units

    // acc[b][0] = packed cols {0,1}, acc[b][1] = packed cols {2,3}
    unsigned long long acc[B][2];
    #pragma unroll
    for (int b = 0; b < B; b++) { acc[b][0] = 0ull; acc[b][1] = 0ull; }

    // One row of packed-FMA work; W is an ulonglong2 (4 cols as 2 packed pairs)
    #define DO_ROW(WV, MI) do {                                              \
        const ulonglong2* ps =                                               \
            reinterpret_cast<const ulonglong2*>(&pre_s2[(MI)][0]);           \
        ulonglong2 pa = ps[0];  /* batches 0,1 */                            \
        ulonglong2 pb = ps[1];  /* batches 2,3 */                            \
        ulonglong2 pc = ps[2];  /* batches 4,5 */                            \
        ulonglong2 pd = ps[3];  /* batches 6,7 */                            \
        FMA2(acc[0][0], (WV).x, pa.x); FMA2(acc[0][1], (WV).y, pa.x);        \
        FMA2(acc[1][0], (WV).x, pa.y); FMA2(acc[1][1], (WV).y, pa.y);        \
        FMA2(acc[2][0], (WV).x, pb.x); FMA2(acc[2][1], (WV).y, pb.x);        \
        FMA2(acc[3][0], (WV).x, pb.y); FMA2(acc[3][1], (WV).y, pb.y);        \
        FMA2(acc[4][0], (WV).x, pc.x); FMA2(acc[4][1], (WV).y, pc.x);        \
        FMA2(acc[5][0], (WV).x, pc.y); FMA2(acc[5][1], (WV).y, pc.y);        \
        FMA2(acc[6][0], (WV).x, pd.x); FMA2(acc[6][1], (WV).y, pd.x);        \
        FMA2(acc[7][0], (WV).x, pd.y); FMA2(acc[7][1], (WV).y, pd.y);        \
    } while (0)

    // Explicit 4-deep load batching: 4 independent LDG.128s issued in program
    // order before any FMA consumes them -> MLP >= 4 per warp.
    #pragma unroll 1
    for (int m = 0; m < ROWS; m += 4) {
        ulonglong2 w0 = Wp[(size_t)(m + 0) * S16];
        ulonglong2 w1 = Wp[(size_t)(m + 1) * S16];
        ulonglong2 w2 = Wp[(size_t)(m + 2) * S16];
        ulonglong2 w3 = Wp[(size_t)(m + 3) * S16];
        DO_ROW(w0, m + 0);
        DO_ROW(w1, m + 1);
        DO_ROW(w2, m + 2);
        DO_ROW(w3, m + 3);
    }
    #undef DO_ROW

    #pragma unroll
    for (int b = 0; b < B; b++) {
        float2 lo = *reinterpret_cast<float2*>(&acc[b][0]);
        float2 hi = *reinterpret_cast<float2*>(&acc[b][1]);
        float4 v = make_float4(lo.x, lo.y, hi.x, hi.y);
        *reinterpret_cast<float4*>(&g_part[((size_t)s * B + b) * N + n0]) = v;
    }
}

// Cooperative reduce: 4 threads per float4 output quad, 16 splits each,
// combined through smem. 256 blocks x 256 threads covers all B*N/4 quads.
#define RTPB 256
#define QUADS_PER_BLOCK (RTPB / 4)   // 64 float4 outputs per block

__global__ void __launch_bounds__(RTPB)
snn_reduce(const float* __restrict__ thr,       // [B][N]
           const float* __restrict__ cst,       // [B][N]
           float* __restrict__ out)             // [B][N]
{
    __shared__ float4 red[RTPB];

    const int t    = threadIdx.x;
    const int ql   = t >> 2;                    // local quad 0..63
    const int k    = t & 3;                     // split group 0..3
    const int quad = blockIdx.x * QUADS_PER_BLOCK + ql;
    const int base = quad * 4;                  // float index into [B*N]

    // 16 independent LDG.128s, front-batched into a register array -> MLP~16.
    const float4* src = reinterpret_cast<const float4*>(
        &g_part[(size_t)(k * 16) * B * N + base]);
    const size_t plane4 = (size_t)B * N / 4;    // float4 stride between splits

    float4 v[16];
    #pragma unroll
    for (int i = 0; i < 16; i++)
        v[i] = src[(size_t)i * plane4];

    float4 sum = make_float4(0.f, 0.f, 0.f, 0.f);
    #pragma unroll
    for (int i = 0; i < 16; i++) {
        sum.x += v[i].x; sum.y += v[i].y; sum.z += v[i].z; sum.w += v[i].w;
    }

    red[t] = sum;
    __syncthreads();

    if (k == 0) {
        float4 a = red[t + 0];
        float4 b2 = red[t + 1];
        float4 c2 = red[t + 2];
        float4 d2 = red[t + 3];
        float4 s4;
        s4.x = a.x + b2.x + c2.x + d2.x;
        s4.y = a.y + b2.y + c2.y + d2.y;
        s4.z = a.z + b2.z + c2.z + d2.z;
        s4.w = a.w + b2.w + c2.w + d2.w;

        float4 tt = *reinterpret_cast<const float4*>(&thr[base]);
        float4 cc = *reinterpret_cast<const float4*>(&cst[base]);

        float4 o;
        o.x = fminf(fmaxf(s4.x + cc.x - tt.x, 0.f), 0.9f);
        o.y = fminf(fmaxf(s4.y + cc.y - tt.y, 0.f), 0.9f);
        o.z = fminf(fmaxf(s4.z + cc.z - tt.z, 0.f), 0.9f);
        o.w = fminf(fmaxf(s4.w + cc.w - tt.w, 0.f), 0.9f);

        *reinterpret_cast<float4*>(&out[base]) = o;
    }
}

extern "C" void kernel_launch(void* const* d_in, const int* in_sizes, int n_in,
                              void* d_out, int out_size)
{
    const float* pre = (const float*)d_in[0];   // pre_spikes [8,1,8192]
    const float* W   = (const float*)d_in[1];   // W [8192,8192]
    const float* thr = (const float*)d_in[2];   // thr [8,1,8192]
    const float* cst = (const float*)d_in[3];   // const_inp [8,1,8192]
    float* out = (float*)d_out;                 // [8,1,8192]

    dim3 grid(NBLK, SPLITS);                    // 16 x 64 = 1024 blocks
    snn_gemv_split<<<grid, TPB>>>(pre, W);

    // (B*N/4 quads) * 4 threads = B*N threads = 65536 -> 256 blocks
    snn_reduce<<<(B * N) / RTPB, RTPB>>>(thr, cst, out);
}